// round 1
// baseline (speedup 1.0000x reference)
#include <cuda_runtime.h>
#include <cuda_bf16.h>

// Problem constants
#define Bq 16
#define Dq 128
#define Lq 4096
#define Kq 8
#define Nq 1024

#define TM 64        // l-positions per CTA
#define NCHUNK 128   // codes per smem chunk
#define THREADS 256

#define ZQ_ELEMS (Bq*Kq*Dq*Lq)   // 67108864 floats, then indices (B,L,K) as float

// Scratch (allocation-free rule: __device__ globals)
__device__ float g_cnorm[Kq*Nq];          // ||c||^2 per code
__device__ float g_res[Bq*Dq*Lq];         // running residual (B,D,L)

// Shared memory layout (in floats)
#define RES_OFF 0                          // resT[128][64]
#define CBS_OFF (128*64)                   // cbs[128][129]  (also reused as sel[64][129])
#define CN_OFF  (CBS_OFF + 128*129)        // cnormS[1024]
#define RI_OFF  (CN_OFF + 1024)            // rowIdx[64] (ints)
#define SMEM_FLOATS (RI_OFF + 64)

__global__ void cnorm_kernel(const float* __restrict__ cb) {
    int gw   = (blockIdx.x * blockDim.x + threadIdx.x) >> 5;  // one warp per code
    int lane = threadIdx.x & 31;
    if (gw >= Kq * Nq) return;
    float4 v = *(const float4*)&cb[(size_t)gw * Dq + lane * 4];
    float s = v.x*v.x + v.y*v.y + v.z*v.z + v.w*v.w;
    #pragma unroll
    for (int off = 16; off > 0; off >>= 1)
        s += __shfl_xor_sync(0xffffffffu, s, off);
    if (lane == 0) g_cnorm[gw] = s;
}

__global__ void __launch_bounds__(THREADS, 2)
vq_step(const float* __restrict__ x, const float* __restrict__ cb,
        float* __restrict__ out, float* __restrict__ idxOut, int k)
{
    extern __shared__ float sm[];
    float* resT   = sm + RES_OFF;   // [128 d][64 m]
    float* cbs    = sm + CBS_OFF;   // [128 n][129]
    float* cnormS = sm + CN_OFF;    // [1024]
    int*   rowIdx = (int*)(sm + RI_OFF);

    const int tid = threadIdx.x;
    const int b   = blockIdx.y;
    const int l0  = blockIdx.x * TM;
    const int tm  = tid >> 5;   // warp id: rows 8*tm .. 8*tm+7
    const int tn  = tid & 31;   // lane:    cols tn + 32*j

    // codebook norms for this stage
    for (int i = tid; i < Nq; i += THREADS)
        cnormS[i] = g_cnorm[k * Nq + i];

    // residual tile: resT[d][m] (k==0 reads x directly; else running residual)
    {
        const float* src = (k == 0) ? x : g_res;
        #pragma unroll
        for (int it = 0; it < 32; ++it) {
            int d = it * 4 + (tid >> 6);
            int m = tid & 63;
            resT[d * 64 + m] = src[((size_t)b * Dq + d) * Lq + l0 + m];
        }
    }
    __syncthreads();

    float bestv[8];
    int   bestn[8];
    #pragma unroll
    for (int i = 0; i < 8; ++i) { bestv[i] = 3.4e38f; bestn[i] = 0; }

    for (int chunk = 0; chunk < Nq / NCHUNK; ++chunk) {
        // load chunk of 128 code rows into cbs[n][d] (pitch 129)
        {
            #pragma unroll
            for (int rr = 0; rr < 16; ++rr) {
                int row = tm * 16 + rr;
                const float4 v = *(const float4*)
                    &cb[((size_t)(k * Nq + chunk * NCHUNK + row)) * Dq + tn * 4];
                float* dst = &cbs[row * 129 + tn * 4];
                dst[0] = v.x; dst[1] = v.y; dst[2] = v.z; dst[3] = v.w;
            }
        }
        __syncthreads();

        float acc[8][4];
        #pragma unroll
        for (int i = 0; i < 8; ++i)
            #pragma unroll
            for (int j = 0; j < 4; ++j)
                acc[i][j] = 0.0f;

        #pragma unroll 4
        for (int kk = 0; kk < Dq; ++kk) {
            float4 a0 = *(const float4*)&resT[kk * 64 + tm * 8];
            float4 a1 = *(const float4*)&resT[kk * 64 + tm * 8 + 4];
            float av[8] = {a0.x, a0.y, a0.z, a0.w, a1.x, a1.y, a1.z, a1.w};
            float bv[4];
            #pragma unroll
            for (int j = 0; j < 4; ++j)
                bv[j] = cbs[(tn + 32 * j) * 129 + kk];
            #pragma unroll
            for (int i = 0; i < 8; ++i)
                #pragma unroll
                for (int j = 0; j < 4; ++j)
                    acc[i][j] = fmaf(av[i], bv[j], acc[i][j]);
        }

        // distances (||r||^2 dropped: constant per row) + running argmin
        #pragma unroll
        for (int j = 0; j < 4; ++j) {
            int n = chunk * NCHUNK + tn + 32 * j;
            float cn = cnormS[n];
            #pragma unroll
            for (int i = 0; i < 8; ++i) {
                float s = cn - 2.0f * acc[i][j];
                if (s < bestv[i] || (s == bestv[i] && n < bestn[i])) {
                    bestv[i] = s; bestn[i] = n;
                }
            }
        }
        __syncthreads();   // before next chunk overwrites cbs
    }

    // warp argmin reduction (tie -> smallest n, matching argmin-first semantics)
    #pragma unroll
    for (int i = 0; i < 8; ++i) {
        float bv = bestv[i]; int bn = bestn[i];
        #pragma unroll
        for (int off = 16; off > 0; off >>= 1) {
            float ov = __shfl_xor_sync(0xffffffffu, bv, off);
            int   on = __shfl_xor_sync(0xffffffffu, bn, off);
            if (ov < bv || (ov == bv && on < bn)) { bv = ov; bn = on; }
        }
        if (tn == 0) rowIdx[tm * 8 + i] = bn;
    }
    __syncthreads();

    // indices output (B, L, K), cast to float
    if (tid < TM)
        idxOut[((size_t)b * Lq + l0 + tid) * Kq + k] = (float)rowIdx[tid];

    // stage the 64 selected code rows into smem (reuse cbs region): sel[m][d], pitch 129
    {
        #pragma unroll
        for (int rr = 0; rr < 8; ++rr) {
            int row = tm * 8 + rr;
            int idx = rowIdx[row];
            float4 v = *(const float4*)&cb[((size_t)(k * Nq + idx)) * Dq + tn * 4];
            float* dst = &cbs[row * 129 + tn * 4];
            dst[0] = v.x; dst[1] = v.y; dst[2] = v.z; dst[3] = v.w;
        }
    }
    __syncthreads();

    // cumulative output + residual update, all l-coalesced
    {
        size_t outBase  = (((size_t)b * Kq + k) * Dq) * Lq;
        size_t prevBase = (k > 0) ? ((((size_t)b * Kq + (k - 1)) * Dq) * Lq) : 0;
        #pragma unroll
        for (int it = 0; it < 32; ++it) {
            int d = it * 4 + (tid >> 6);
            int m = tid & 63;
            float code = cbs[m * 129 + d];
            float prev = (k > 0) ? out[prevBase + (size_t)d * Lq + l0 + m] : 0.0f;
            out[outBase + (size_t)d * Lq + l0 + m] = prev + code;
            g_res[((size_t)b * Dq + d) * Lq + l0 + m] = resT[d * 64 + m] - code;
        }
    }
}

extern "C" void kernel_launch(void* const* d_in, const int* in_sizes, int n_in,
                              void* d_out, int out_size)
{
    const float* x  = (const float*)d_in[0];
    const float* cb = (const float*)d_in[1];
    float* out    = (float*)d_out;
    float* idxOut = out + (size_t)ZQ_ELEMS;

    cudaFuncSetAttribute(vq_step, cudaFuncAttributeMaxDynamicSharedMemorySize,
                         SMEM_FLOATS * 4);

    cnorm_kernel<<<(Kq * Nq * 32) / 256, 256>>>(cb);
    for (int k = 0; k < Kq; ++k)
        vq_step<<<dim3(Lq / TM, Bq), THREADS, SMEM_FLOATS * 4>>>(x, cb, out, idxOut, k);
}

// round 2
// speedup vs baseline: 1.2003x; 1.2003x over previous
#include <cuda_runtime.h>
#include <cuda_bf16.h>

// Problem constants
#define Bq 16
#define Dq 128
#define Lq 4096
#define Kq 8
#define Nq 1024

#define TM 64        // l-positions per CTA
#define NCHUNK 128   // codes per smem chunk
#define THREADS 256
#define PITCH 132    // floats per smem row (128 + 4 pad): conflict-free LDS.128

#define ZQ_ELEMS (Bq*Kq*Dq*Lq)

// Scratch (allocation-free rule: __device__ globals)
__device__ float g_cnorm[Kq*Nq];          // ||c||^2 per code
__device__ float g_res[Bq*Dq*Lq];         // running residual (B,D,L)

// Shared memory layout (in floats)
#define RES_OFF 0                          // resT[64 m][PITCH]   (d-minor)
#define CBS_OFF (64*PITCH)                 // cbs[128 n][PITCH]   (d-minor) / reused as sel[64 m][PITCH]
#define CN_OFF  (CBS_OFF + 128*PITCH)      // cnormS[1024]
#define RI_OFF  (CN_OFF + 1024)            // rowIdx[64] (ints)
#define SMEM_FLOATS (RI_OFF + 64)

__global__ void cnorm_kernel(const float* __restrict__ cb) {
    int gw   = (blockIdx.x * blockDim.x + threadIdx.x) >> 5;  // one warp per code
    int lane = threadIdx.x & 31;
    if (gw >= Kq * Nq) return;
    float4 v = *(const float4*)&cb[(size_t)gw * Dq + lane * 4];
    float s = v.x*v.x + v.y*v.y + v.z*v.z + v.w*v.w;
    #pragma unroll
    for (int off = 16; off > 0; off >>= 1)
        s += __shfl_xor_sync(0xffffffffu, s, off);
    if (lane == 0) g_cnorm[gw] = s;
}

__global__ void __launch_bounds__(THREADS, 2)
vq_step(const float* __restrict__ x, const float* __restrict__ cb,
        float* __restrict__ out, float* __restrict__ idxOut, int k)
{
    extern __shared__ float sm[];
    float* resT   = sm + RES_OFF;   // [64 m][PITCH]
    float* cbs    = sm + CBS_OFF;   // [128 n][PITCH]
    float* cnormS = sm + CN_OFF;    // [1024]
    int*   rowIdx = (int*)(sm + RI_OFF);

    const int tid = threadIdx.x;
    const int b   = blockIdx.y;
    const int l0  = blockIdx.x * TM;
    const int tm  = tid >> 5;   // warp id: rows 8*tm .. 8*tm+7
    const int tn  = tid & 31;   // lane:    cols tn + 32*j

    // codebook norms for this stage
    for (int i = tid; i < Nq; i += THREADS)
        cnormS[i] = g_cnorm[k * Nq + i];

    // residual tile: resT[m][d] (k==0 reads x directly; else running residual)
    {
        const float* src = (k == 0) ? x : g_res;
        #pragma unroll
        for (int it = 0; it < 32; ++it) {
            int d = it * 4 + (tid >> 6);
            int m = tid & 63;
            resT[m * PITCH + d] = src[((size_t)b * Dq + d) * Lq + l0 + m];
        }
    }
    __syncthreads();

    float bestv[8];
    int   bestn[8];
    #pragma unroll
    for (int i = 0; i < 8; ++i) { bestv[i] = 3.4e38f; bestn[i] = 0; }

    for (int chunk = 0; chunk < Nq / NCHUNK; ++chunk) {
        // load chunk of 128 code rows into cbs[n][d] (same orientation as global)
        {
            const float4* cb4 = (const float4*)
                &cb[((size_t)(k * Nq + chunk * NCHUNK)) * Dq];
            #pragma unroll
            for (int it = 0; it < 16; ++it) {
                int f   = tid + THREADS * it;   // float4 index within chunk
                int row = f >> 5;               // 32 float4 per row
                int c4  = f & 31;
                *(float4*)&cbs[row * PITCH + c4 * 4] = cb4[row * 32 + c4];
            }
        }
        __syncthreads();

        float acc[8][4];
        #pragma unroll
        for (int i = 0; i < 8; ++i)
            #pragma unroll
            for (int j = 0; j < 4; ++j)
                acc[i][j] = 0.0f;

        #pragma unroll 2
        for (int kk4 = 0; kk4 < Dq / 4; ++kk4) {
            float4 a[8];
            #pragma unroll
            for (int i = 0; i < 8; ++i)
                a[i] = *(const float4*)&resT[(tm * 8 + i) * PITCH + kk4 * 4];
            float4 bv[4];
            #pragma unroll
            for (int j = 0; j < 4; ++j)
                bv[j] = *(const float4*)&cbs[(tn + 32 * j) * PITCH + kk4 * 4];
            #pragma unroll
            for (int i = 0; i < 8; ++i) {
                #pragma unroll
                for (int j = 0; j < 4; ++j) {
                    acc[i][j] = fmaf(a[i].x, bv[j].x, acc[i][j]);
                    acc[i][j] = fmaf(a[i].y, bv[j].y, acc[i][j]);
                    acc[i][j] = fmaf(a[i].z, bv[j].z, acc[i][j]);
                    acc[i][j] = fmaf(a[i].w, bv[j].w, acc[i][j]);
                }
            }
        }

        // distances (||r||^2 dropped: constant per row) + running argmin
        #pragma unroll
        for (int j = 0; j < 4; ++j) {
            int n = chunk * NCHUNK + tn + 32 * j;
            float cn = cnormS[n];
            #pragma unroll
            for (int i = 0; i < 8; ++i) {
                float s = cn - 2.0f * acc[i][j];
                if (s < bestv[i] || (s == bestv[i] && n < bestn[i])) {
                    bestv[i] = s; bestn[i] = n;
                }
            }
        }
        __syncthreads();   // before next chunk overwrites cbs
    }

    // warp argmin reduction (tie -> smallest n)
    #pragma unroll
    for (int i = 0; i < 8; ++i) {
        float bv = bestv[i]; int bn = bestn[i];
        #pragma unroll
        for (int off = 16; off > 0; off >>= 1) {
            float ov = __shfl_xor_sync(0xffffffffu, bv, off);
            int   on = __shfl_xor_sync(0xffffffffu, bn, off);
            if (ov < bv || (ov == bv && on < bn)) { bv = ov; bn = on; }
        }
        if (tn == 0) rowIdx[tm * 8 + i] = bn;
    }
    __syncthreads();

    // indices output (B, L, K), cast to float
    if (tid < TM)
        idxOut[((size_t)b * Lq + l0 + tid) * Kq + k] = (float)rowIdx[tid];

    // stage the 64 selected code rows into smem (reuse cbs region): sel[m][d]
    {
        #pragma unroll
        for (int rr = 0; rr < 8; ++rr) {
            int row = tm * 8 + rr;
            int idx = rowIdx[row];
            float4 v = *(const float4*)&cb[((size_t)(k * Nq + idx)) * Dq + tn * 4];
            *(float4*)&cbs[row * PITCH + tn * 4] = v;
        }
    }
    __syncthreads();

    // cumulative output + residual update, all l-coalesced
    {
        size_t outBase  = (((size_t)b * Kq + k) * Dq) * Lq;
        size_t prevBase = (k > 0) ? ((((size_t)b * Kq + (k - 1)) * Dq) * Lq) : 0;
        #pragma unroll
        for (int it = 0; it < 32; ++it) {
            int d = it * 4 + (tid >> 6);
            int m = tid & 63;
            float code = cbs[m * PITCH + d];
            float prev = (k > 0) ? out[prevBase + (size_t)d * Lq + l0 + m] : 0.0f;
            out[outBase + (size_t)d * Lq + l0 + m] = prev + code;
            g_res[((size_t)b * Dq + d) * Lq + l0 + m] = resT[m * PITCH + d] - code;
        }
    }
}

extern "C" void kernel_launch(void* const* d_in, const int* in_sizes, int n_in,
                              void* d_out, int out_size)
{
    const float* x  = (const float*)d_in[0];
    const float* cb = (const float*)d_in[1];
    float* out    = (float*)d_out;
    float* idxOut = out + (size_t)ZQ_ELEMS;

    cudaFuncSetAttribute(vq_step, cudaFuncAttributeMaxDynamicSharedMemorySize,
                         SMEM_FLOATS * 4);

    cnorm_kernel<<<(Kq * Nq * 32) / 256, 256>>>(cb);
    for (int k = 0; k < Kq; ++k)
        vq_step<<<dim3(Lq / TM, Bq), THREADS, SMEM_FLOATS * 4>>>(x, cb, out, idxOut, k);
}